// round 7
// baseline (speedup 1.0000x reference)
#include <cuda_runtime.h>

#define Bsz 64
#define Dd  512
#define Ll  8192
#define NLn 1000

typedef unsigned long long ull;

// Intermediates (device globals; allocations forbidden).
// Never passed as host-side kernel args — kernels reference them directly.
__device__ __align__(16) float g_ye0 [Bsz*Dd];
__device__ __align__(16) float g_ye1 [Bsz*Dd];
__device__ __align__(16) float g_ye2 [Bsz*Dd];
__device__ __align__(16) float g_zz1 [Bsz*Dd];
__device__ __align__(16) float g_zz2 [Bsz*Dd];
__device__ __align__(16) float g_s_pad[Bsz*32];   // s[b] at b*32 (sector-spread atomics)

__device__ __forceinline__ void cp_async16(void* dst, const void* src) {
    unsigned s = (unsigned)__cvta_generic_to_shared(dst);
    asm volatile("cp.async.cg.shared.global [%0], [%1], 16;" :: "r"(s), "l"(src) : "memory");
}
__device__ __forceinline__ ull pack2(float lo, float hi) {
    ull r; asm("mov.b64 %0, {%1, %2};" : "=l"(r) : "f"(lo), "f"(hi)); return r;
}
__device__ __forceinline__ void unpack2(float& lo, float& hi, ull v) {
    asm("mov.b64 {%0, %1}, %2;" : "=f"(lo), "=f"(hi) : "l"(v));
}
__device__ __forceinline__ void ffma2(ull& d, ull a, ull b) {
    asm("fma.rn.f32x2 %0, %1, %2, %0;" : "+l"(d) : "l"(a), "l"(b));
}
__device__ __forceinline__ void red4(float* p, float v0, float v1, float v2, float v3) {
    asm volatile("red.global.add.v4.f32 [%0], {%1,%2,%3,%4};"
                 :: "l"(p), "f"(v0), "f"(v1), "f"(v2), "f"(v3) : "memory");
}

// ---------------------------------------------------------------------------
// K1: ye0 gather, stage-1 residual inits, zero stage-2 accumulators + s.
// ---------------------------------------------------------------------------
__global__ void k_prep(const float* __restrict__ z, const int* __restrict__ y,
                       const float* __restrict__ W_yemb, const float* __restrict__ b_yemb,
                       const float* __restrict__ by1, const float* __restrict__ bz1) {
    int b = blockIdx.x;
    int e = blockIdx.y * 128 + threadIdx.x;
    int yb = __ldg(y + b);
    float v  = __ldg(W_yemb + e*NLn + yb) + b_yemb[e];
    float zv = z[b*Dd + e];
    g_ye0[b*Dd + e] = v;
    g_ye1[b*Dd + e] = v  + by1[e];
    g_zz1[b*Dd + e] = zv + bz1[e];
    g_ye2[b*Dd + e] = 0.f;
    g_zz2[b*Dd + e] = 0.f;
    if (blockIdx.y == 0 && threadIdx.x == 0) g_s_pad[b*32] = 0.f;
}

// ---------------------------------------------------------------------------
// Small residual GEMM (unchanged from passing R5/R6 kernel).
// ---------------------------------------------------------------------------
template<int STAGE>
__global__ void __launch_bounds__(256) k_small(const float* __restrict__ z,
                                               const float* __restrict__ Wy,
                                               const float* __restrict__ Wz,
                                               const float* __restrict__ b2y,
                                               const float* __restrict__ b2z,
                                               const float* __restrict__ w_proj) {
    __shared__ float sA[64*68];   // [b][k] pad 68 (broadcast-read conflict-free)
    __shared__ float sW[64*32];   // [k][e] transposed
    const float* A; const float* W; const float* b2; float* C;
    if (STAGE == 1) {
        if (blockIdx.y == 0) { A = g_ye0; W = Wy; b2 = nullptr; C = g_ye1; }
        else                 { A = z;     W = Wz; b2 = nullptr; C = g_zz1; }
    } else {
        if (blockIdx.y == 0) { A = g_ye1; W = Wy; b2 = b2y; C = g_ye2; }
        else                 { A = g_zz1; W = Wz; b2 = b2z; C = g_zz2; }
    }
    const int t  = threadIdx.x;
    const int e0 = (blockIdx.x & 15) * 32;
    const int k0 = (blockIdx.x >> 4) * 64;

    #pragma unroll
    for (int r = 0; r < 4; r++) {
        int id = t + 256*r;              // 0..1023
        int b = id >> 4, k4 = id & 15;
        cp_async16(&sA[b*68 + 4*k4], A + b*Dd + k0 + 4*k4);
    }
    asm volatile("cp.async.commit_group;" ::: "memory");
    float4 wv[2]; int we[2], wk[2];
    #pragma unroll
    for (int r = 0; r < 2; r++) {
        int id = t + 256*r;              // 0..511
        we[r] = id >> 4; wk[r] = id & 15;
        wv[r] = *(const float4*)(W + (e0 + we[r])*Dd + k0 + 4*wk[r]);
    }
    #pragma unroll
    for (int r = 0; r < 2; r++) {
        sW[(4*wk[r] + 0)*32 + we[r]] = wv[r].x;
        sW[(4*wk[r] + 1)*32 + we[r]] = wv[r].y;
        sW[(4*wk[r] + 2)*32 + we[r]] = wv[r].z;
        sW[(4*wk[r] + 3)*32 + we[r]] = wv[r].w;
    }
    asm volatile("cp.async.wait_group 0;" ::: "memory");
    __syncthreads();

    const int b  = t >> 2;     // 0..63
    const int eg = t & 3;      // e-octet: e0 + eg*8 .. +7
    ull acc[4] = {0, 0, 0, 0};

    #pragma unroll 8
    for (int k = 0; k < 64; k++) {
        float a = sA[b*68 + k];
        ull ap = pack2(a, a);
        ulonglong2 wA = *(const ulonglong2*)&sW[k*32 + eg*8];
        ulonglong2 wB = *(const ulonglong2*)&sW[k*32 + eg*8 + 4];
        ffma2(acc[0], ap, wA.x);
        ffma2(acc[1], ap, wA.y);
        ffma2(acc[2], ap, wB.x);
        ffma2(acc[3], ap, wB.y);
    }

    float v[8];
    unpack2(v[0], v[1], acc[0]);
    unpack2(v[2], v[3], acc[1]);
    unpack2(v[4], v[5], acc[2]);
    unpack2(v[6], v[7], acc[3]);
    const int eo = e0 + eg*8;
    if (STAGE == 2 && k0 == 0) {
        float4 p0 = *(const float4*)&A[b*Dd + eo];
        float4 p1 = *(const float4*)&A[b*Dd + eo + 4];
        float4 q0 = *(const float4*)&b2[eo];
        float4 q1 = *(const float4*)&b2[eo + 4];
        v[0] += p0.x + q0.x; v[1] += p0.y + q0.y;
        v[2] += p0.z + q0.z; v[3] += p0.w + q0.w;
        v[4] += p1.x + q1.x; v[5] += p1.y + q1.y;
        v[6] += p1.z + q1.z; v[7] += p1.w + q1.w;
    }
    red4(&C[b*Dd + eo],     v[0], v[1], v[2], v[3]);
    red4(&C[b*Dd + eo + 4], v[4], v[5], v[6], v[7]);

    if (STAGE == 2 && blockIdx.y == 0) {
        float4 wp0 = *(const float4*)&w_proj[eo];
        float4 wp1 = *(const float4*)&w_proj[eo + 4];
        float sp = v[0]*wp0.x + v[1]*wp0.y + v[2]*wp0.z + v[3]*wp0.w
                 + v[4]*wp1.x + v[5]*wp1.y + v[6]*wp1.z + v[7]*wp1.w;
        sp += __shfl_xor_sync(0xffffffffu, sp, 1);
        sp += __shfl_xor_sync(0xffffffffu, sp, 2);
        if (eg == 0) atomicAdd(&g_s_pad[b*32], sp);
    }
}

// ---------------------------------------------------------------------------
// K4: out[b,l] = s[b] * dot(zz2[b,:], W_zlat[l,:])
// K-paired FFMA2. CTA 64b x 32l, 128 threads, thread tile 8b x 2l (16 accs).
// Per warp per 4k: a = 8 LDS.128 (broadcast, 1 wf ea) + w = 2 LDS.128 (2 wf ea)
// = 12 wf vs 64 fma-issue-cycles -> fma-bound with 5x margin.
// Grid 256 -> ~2 CTAs/SM co-resident (16 warps) for latency cross-coverage.
// ---------------------------------------------------------------------------
#define KCH 32            // k per chunk
#define SSTR 36           // row stride in floats (32 + 4 pad, 16B-aligned)
__global__ void __launch_bounds__(128) k_big(const float* __restrict__ Wz,
                                             float* __restrict__ out) {
    __shared__ float sA[2][64*SSTR];   // [b][k] row-major  (9216 B each)
    __shared__ float sW[2][32*SSTR];   // [l][k] row-major  (4608 B each)
    const int t    = threadIdx.x;
    const int l0   = blockIdx.x * 32;
    const int lgrp = t & 15;           // l = l0 + lgrp + 16j   (j=0,1)
    const int bgrp = t >> 4;           // b = 8*bgrp + i        (i=0..7)

    auto load = [&](int buf, int c) {
        // A: 64 rows x 32 k = 512 f4 -> 4 per thread
        #pragma unroll
        for (int r = 0; r < 4; r++) {
            int id  = t + 128*r;       // 0..511
            int row = id >> 3, k4 = id & 7;
            cp_async16(&sA[buf][row*SSTR + 4*k4], g_zz2 + row*Dd + c*KCH + 4*k4);
        }
        // W: 32 rows x 32 k = 256 f4 -> 2 per thread
        #pragma unroll
        for (int r = 0; r < 2; r++) {
            int id  = t + 128*r;       // 0..255
            int row = id >> 3, k4 = id & 7;
            cp_async16(&sW[buf][row*SSTR + 4*k4], Wz + (l0 + row)*Dd + c*KCH + 4*k4);
        }
        asm volatile("cp.async.commit_group;" ::: "memory");
    };

    ull acc[8][2];
    #pragma unroll
    for (int i = 0; i < 8; i++) { acc[i][0] = 0; acc[i][1] = 0; }

    load(0, 0);
    #pragma unroll 1
    for (int c = 0; c < 16; c++) {
        const int cur = c & 1;
        asm volatile("cp.async.wait_group 0;" ::: "memory");  // chunk c arrived
        __syncthreads();               // all arrived; prior reads of other buf done
        if (c < 15) load(cur ^ 1, c + 1);   // prefetch overlaps compute
        const float* Ab = sA[cur];
        const float* Wb = sW[cur];
        #pragma unroll
        for (int kk = 0; kk < KCH/4; kk++) {
            ulonglong2 w0 = *(const ulonglong2*)&Wb[lgrp*SSTR + 4*kk];
            ulonglong2 w1 = *(const ulonglong2*)&Wb[(lgrp + 16)*SSTR + 4*kk];
            #pragma unroll
            for (int i = 0; i < 8; i++) {
                ulonglong2 a = *(const ulonglong2*)&Ab[(8*bgrp + i)*SSTR + 4*kk];
                ffma2(acc[i][0], a.x, w0.x);
                ffma2(acc[i][0], a.y, w0.y);
                ffma2(acc[i][1], a.x, w1.x);
                ffma2(acc[i][1], a.y, w1.y);
            }
        }
    }

    // reduce k-pairs, scale by s[b], store
    #pragma unroll
    for (int i = 0; i < 8; i++) {
        const int b = 8*bgrp + i;
        const float s = g_s_pad[b*32];
        #pragma unroll
        for (int j = 0; j < 2; j++) {
            float lo, hi;
            unpack2(lo, hi, acc[i][j]);
            out[b*Ll + l0 + lgrp + 16*j] = (lo + hi) * s;
        }
    }
}

extern "C" void kernel_launch(void* const* d_in, const int* in_sizes, int n_in,
                              void* d_out, int out_size) {
    const float* z      = (const float*)d_in[0];
    const int*   y      = (const int*)  d_in[1];
    const float* W_yemb = (const float*)d_in[2];
    const float* b_yemb = (const float*)d_in[3];
    const float* Wy1    = (const float*)d_in[4];
    const float* by1    = (const float*)d_in[5];
    const float* Wy2    = (const float*)d_in[6];
    const float* by2    = (const float*)d_in[7];
    const float* Wz1    = (const float*)d_in[8];
    const float* bz1    = (const float*)d_in[9];
    const float* Wz2    = (const float*)d_in[10];
    const float* bz2    = (const float*)d_in[11];
    const float* W_zlat = (const float*)d_in[12];
    const float* w_proj = (const float*)d_in[13];
    float* out = (float*)d_out;

    k_prep<<<dim3(Bsz, 4), 128>>>(z, y, W_yemb, b_yemb, by1, bz1);
    k_small<1><<<dim3(128, 2), 256>>>(z, Wy1, Wz1, nullptr, nullptr, nullptr);
    k_small<2><<<dim3(128, 2), 256>>>(z, Wy2, Wz2, by2, bz2, w_proj);
    k_big<<<Ll/32, 128>>>(W_zlat, out);
}